// round 12
// baseline (speedup 1.0000x reference)
#include <cuda_runtime.h>
#include <math.h>

// Problem constants
#define B_   64
#define S_   256
#define H_   768
#define G_   3072      // 4*H
#define BS_  16384     // B*S
#define TOUT 2

// Persistent recurrence config: each CTA owns all 64 rows, 6 h-cols / 24 gate-cols.
// 256 threads = 2 K-groups x 128; group g reduces K in [g*384, g*384+384).
#define NBLK 128
#define PT   256
#define HC   6
#define COLS 24
#define CK   64        // K chunk per staging step (6 chunks per group)
#define KHALF 384
#define LDA  68        // As row stride (floats), 16B-aligned
#define LDW  772       // Ws row stride (floats), 16B-aligned, conflict-free B LDS.128

// ---------------- scratch (device globals; no allocation allowed) -----------
__device__ float g_act0[BS_ * H_];       // emb, later layer-1 output
__device__ float g_act1[BS_ * H_];       // layer-0 output
__device__ float g_gates[BS_ * G_];      // precomputed x@Wx + b
__device__ float g_hbuf[2][B_ * H_];     // double-buffered hidden state
__device__ float g_pool[B_ * H_];

__device__ unsigned g_bar_cnt = 0;
__device__ volatile unsigned g_bar_gen = 0;

// ---------------- packed f32x2 FMA helpers (Blackwell FFMA2) ----------------
typedef unsigned long long ull;

__device__ __forceinline__ ull fma2(ull a, ull b, ull c) {
    ull d;
    asm("fma.rn.f32x2 %0, %1, %2, %3;" : "=l"(d) : "l"(a), "l"(b), "l"(c));
    return d;
}
__device__ __forceinline__ float2 unpack2(ull v) {
    float x, y;
    asm("mov.b64 {%0, %1}, %2;" : "=f"(x), "=f"(y) : "l"(v));
    return make_float2(x, y);
}
__device__ __forceinline__ ull pack2(float x, float y) {
    ull r;
    asm("mov.b64 %0, {%1, %2};" : "=l"(r) : "f"(x), "f"(y));
    return r;
}

// group-scoped named barrier (128 threads each; ids 1 and 2)
#define GRP_BAR(g) asm volatile("bar.sync %0, 128;" :: "r"(1 + (g)) : "memory")

// ---------------- central grid barrier (all NBLK CTAs co-resident) ----------
__device__ __forceinline__ void grid_barrier(unsigned& gen) {
    __syncthreads();
    if (threadIdx.x == 0) {
        __threadfence();
        unsigned target = gen + 1u;
        unsigned old = atomicAdd(&g_bar_cnt, 1u);
        if (old == NBLK - 1) {
            g_bar_cnt = 0;
            __threadfence();
            g_bar_gen = target;
        } else {
            while (g_bar_gen != target) { __nanosleep(32); }
        }
        __threadfence();
    }
    __syncthreads();
    gen += 1u;
}

// ---------------- embedding gather ------------------------------------------
__global__ void k_embed(const int* __restrict__ ids, const float* __restrict__ table) {
    int row = blockIdx.x;
    int id  = ids[row];
    const float4* src = (const float4*)(table + (size_t)id * H_);
    float4*       dst = (float4*)(g_act0 + (size_t)row * H_);
    dst[threadIdx.x] = src[threadIdx.x];       // 192 threads * float4 = 768
}

// ---------------- big GEMM: gates = act @ Wx + bias (2-stage pipelined) -----
#define BM  128
#define BNB 128
#define BKB 16
__global__ void __launch_bounds__(256, 2) k_gemm_bias(int srcSel,
                                                      const float* __restrict__ Wx,
                                                      const float* __restrict__ bias) {
    const float* A = srcSel ? g_act1 : g_act0;
    __shared__ float As[2][BKB][BM + 4];
    __shared__ float Bs[2][BKB][BNB];

    int tid = threadIdx.x;
    int bm = blockIdx.y, bn = blockIdx.x;
    int tx = tid & 15, ty = tid >> 4;
    int m0 = ty * 8, n0 = tx * 8;

    int aR[2], aC[2], bR[2], bC[2];
#pragma unroll
    for (int it = 0; it < 2; it++) {
        int id = tid + it * 256;
        aR[it] = id >> 2;  aC[it] = (id & 3) * 4;
        bR[it] = id >> 5;  bC[it] = (id & 31) * 4;
    }

    ull acc[8][4];
#pragma unroll
    for (int i = 0; i < 8; i++)
#pragma unroll
        for (int j = 0; j < 4; j++) acc[i][j] = 0ULL;

    const float* Ab = A + (size_t)bm * BM * H_;
    const float* Wb = Wx + bn * BNB;

    float4 rA[2], rB[2];
#pragma unroll
    for (int it = 0; it < 2; it++) {
        rA[it] = *(const float4*)(Ab + (size_t)aR[it] * H_ + aC[it]);
        rB[it] = *(const float4*)(Wb + (size_t)bR[it] * G_ + bC[it]);
    }
#pragma unroll
    for (int it = 0; it < 2; it++) {
        As[0][aC[it] + 0][aR[it]] = rA[it].x;
        As[0][aC[it] + 1][aR[it]] = rA[it].y;
        As[0][aC[it] + 2][aR[it]] = rA[it].z;
        As[0][aC[it] + 3][aR[it]] = rA[it].w;
        *(float4*)&Bs[0][bR[it]][bC[it]] = rB[it];
    }

    int stage = 0;
    for (int k0 = 0; k0 < H_; k0 += BKB) {
        __syncthreads();
        bool more = (k0 + BKB) < H_;
        if (more) {
#pragma unroll
            for (int it = 0; it < 2; it++) {
                rA[it] = *(const float4*)(Ab + (size_t)aR[it] * H_ + (k0 + BKB) + aC[it]);
                rB[it] = *(const float4*)(Wb + (size_t)(k0 + BKB + bR[it]) * G_ + bC[it]);
            }
        }
#pragma unroll
        for (int k = 0; k < BKB; k++) {
            float4 alo = *(const float4*)&As[stage][k][m0];
            float4 ahi = *(const float4*)&As[stage][k][m0 + 4];
            float4 blo = *(const float4*)&Bs[stage][k][n0];
            float4 bhi = *(const float4*)&Bs[stage][k][n0 + 4];
            ull b2[4] = { pack2(blo.x, blo.y), pack2(blo.z, blo.w),
                          pack2(bhi.x, bhi.y), pack2(bhi.z, bhi.w) };
            float av[8] = { alo.x, alo.y, alo.z, alo.w, ahi.x, ahi.y, ahi.z, ahi.w };
#pragma unroll
            for (int i = 0; i < 8; i++) {
                ull ad = pack2(av[i], av[i]);
#pragma unroll
                for (int j = 0; j < 4; j++) acc[i][j] = fma2(ad, b2[j], acc[i][j]);
            }
        }
        if (more) {
            int ns = stage ^ 1;
#pragma unroll
            for (int it = 0; it < 2; it++) {
                As[ns][aC[it] + 0][aR[it]] = rA[it].x;
                As[ns][aC[it] + 1][aR[it]] = rA[it].y;
                As[ns][aC[it] + 2][aR[it]] = rA[it].z;
                As[ns][aC[it] + 3][aR[it]] = rA[it].w;
                *(float4*)&Bs[ns][bR[it]][bC[it]] = rB[it];
            }
            stage = ns;
        }
    }

    float bv[8];
#pragma unroll
    for (int j = 0; j < 8; j++) bv[j] = bias[bn * BNB + n0 + j];
#pragma unroll
    for (int i = 0; i < 8; i++) {
        float* Crow = g_gates + (size_t)(bm * BM + m0 + i) * G_ + bn * BNB + n0;
        float o[8];
#pragma unroll
        for (int j = 0; j < 4; j++) {
            float2 p = unpack2(acc[i][j]);
            o[2 * j]     = p.x + bv[2 * j];
            o[2 * j + 1] = p.y + bv[2 * j + 1];
        }
        *(float4*)(Crow)     = make_float4(o[0], o[1], o[2], o[3]);
        *(float4*)(Crow + 4) = make_float4(o[4], o[5], o[6], o[7]);
    }
}

// ---------------- persistent LSTM layer kernel (256 thr, K-split, LDS.128) --
__global__ void __launch_bounds__(PT, 1) k_lstm_persist(const float* __restrict__ Wh,
                                                        int dstSel) {
    extern __shared__ float sm[];
    float* Ws = sm;                          // [COLS][LDW]
    float* As = Ws + COLS * LDW;             // [2][64][LDA]  one buffer per group
    float* sg = As + 2 * 64 * LDA;           // [2][4*64*HC]  partial planes

    const int tid = threadIdx.x, bid = blockIdx.x;
    const int grp = tid >> 7, wt = tid & 127;
    float* dst = dstSel ? g_act1 : g_act0;

    // ---- load persistent Wh slice (gathered gate columns) ----
    for (int i = tid; i < COLS * H_; i += PT) {
        int v = i % COLS, k = i / COLS;
        int col = (v / HC) * H_ + bid * HC + (v % HC);
        Ws[v * LDW + k] = Wh[(size_t)k * G_ + col];
    }

    // ---- pointwise ownership: 384 elems over 256 threads (<=2 each) ----
    int pb[2], pj[2], pjl[2];
    float cr[2];
#pragma unroll
    for (int e = 0; e < 2; e++) {
        int idx = tid + e * PT;
        if (idx < 64 * HC) {
            pb[e]  = idx / HC;
            pjl[e] = idx % HC;
            pj[e]  = bid * HC + pjl[e];
            cr[e]  = 0.f;
            g_hbuf[0][pb[e] * H_ + pj[e]] = 0.f;   // t=0 reads buffer 0
        }
    }

    unsigned gen = g_bar_gen;
    grid_barrier(gen);                       // h zeroed + Ws loaded everywhere

    const int ty = wt >> 3, tx = wt & 7;
    const int r0 = ty * 4, n0 = tx * 3;      // 4 rows x 3 gate-cols per thread
    const int kbase = grp * KHALF;
    float* asg = As + grp * 64 * LDA;

    int gcol[3];
#pragma unroll
    for (int j = 0; j < 3; j++) {
        int v = n0 + j;
        gcol[j] = (v / HC) * H_ + bid * HC + (v % HC);
    }

    float gpre[12];
#pragma unroll
    for (int i = 0; i < 12; i++) gpre[i] = 0.f;
    if (grp == 0) {
#pragma unroll
        for (int i = 0; i < 4; i++)
#pragma unroll
            for (int j = 0; j < 3; j++)
                gpre[i * 3 + j] = g_gates[((size_t)(r0 + i) * S_) * G_ + gcol[j]];
    }

    for (int t = 0; t < S_; t++) {
        const float* hrd = g_hbuf[t & 1];
        float*       hwr = g_hbuf[(t + 1) & 1];

        // prefetch my group's chunk 0 (L1-bypassing)
        float4 pf[8];
#pragma unroll
        for (int ii = 0; ii < 8; ii++) {
            int i = wt + ii * 128;               // 0..1023 = 64 rows x 16 float4
            int r = i >> 4, c4 = (i & 15) << 2;
            pf[ii] = __ldcg((const float4*)(hrd + r * H_ + kbase + c4));
        }

        ull acc[12];
#pragma unroll
        for (int i = 0; i < 12; i++) acc[i] = 0ULL;

        for (int c = 0; c < KHALF / CK; c++) {
            GRP_BAR(grp);                    // group's prior compute done (WAR)
#pragma unroll
            for (int ii = 0; ii < 8; ii++) {
                int i = wt + ii * 128;
                int r = i >> 4, c4 = (i & 15) << 2;
                *(float4*)&asg[r * LDA + c4] = pf[ii];
            }
            GRP_BAR(grp);                    // group's chunk c visible
            if (c + 1 < KHALF / CK) {
#pragma unroll
                for (int ii = 0; ii < 8; ii++) {
                    int i = wt + ii * 128;
                    int r = i >> 4, c4 = (i & 15) << 2;
                    pf[ii] = __ldcg((const float4*)(hrd + r * H_ + kbase + (c + 1) * CK + c4));
                }
            }
            const float* asp = asg + r0 * LDA;
            const float* wsp = Ws + n0 * LDW + kbase + c * CK;
#pragma unroll 4
            for (int k4 = 0; k4 < CK; k4 += 4) {
                longlong2 A0 = *(const longlong2*)(asp + k4);
                longlong2 A1 = *(const longlong2*)(asp + LDA + k4);
                longlong2 A2 = *(const longlong2*)(asp + 2 * LDA + k4);
                longlong2 A3 = *(const longlong2*)(asp + 3 * LDA + k4);
                longlong2 B0 = *(const longlong2*)(wsp + k4);
                longlong2 B1 = *(const longlong2*)(wsp + LDW + k4);
                longlong2 B2 = *(const longlong2*)(wsp + 2 * LDW + k4);
                acc[0]  = fma2(A0.x, B0.x, acc[0]);  acc[1]  = fma2(A1.x, B0.x, acc[1]);
                acc[2]  = fma2(A2.x, B0.x, acc[2]);  acc[3]  = fma2(A3.x, B0.x, acc[3]);
                acc[4]  = fma2(A0.x, B1.x, acc[4]);  acc[5]  = fma2(A1.x, B1.x, acc[5]);
                acc[6]  = fma2(A2.x, B1.x, acc[6]);  acc[7]  = fma2(A3.x, B1.x, acc[7]);
                acc[8]  = fma2(A0.x, B2.x, acc[8]);  acc[9]  = fma2(A1.x, B2.x, acc[9]);
                acc[10] = fma2(A2.x, B2.x, acc[10]); acc[11] = fma2(A3.x, B2.x, acc[11]);
                acc[0]  = fma2(A0.y, B0.y, acc[0]);  acc[1]  = fma2(A1.y, B0.y, acc[1]);
                acc[2]  = fma2(A2.y, B0.y, acc[2]);  acc[3]  = fma2(A3.y, B0.y, acc[3]);
                acc[4]  = fma2(A0.y, B1.y, acc[4]);  acc[5]  = fma2(A1.y, B1.y, acc[5]);
                acc[6]  = fma2(A2.y, B1.y, acc[6]);  acc[7]  = fma2(A3.y, B1.y, acc[7]);
                acc[8]  = fma2(A0.y, B2.y, acc[8]);  acc[9]  = fma2(A1.y, B2.y, acc[9]);
                acc[10] = fma2(A2.y, B2.y, acc[10]); acc[11] = fma2(A3.y, B2.y, acc[11]);
            }
        }

        // write this group's partial sums (+ gpre on group 0)
        {
            float* sgp = sg + grp * (4 * 64 * HC);
#pragma unroll
            for (int j = 0; j < 3; j++) {
                int v = n0 + j;
                int gate = v / HC, jl = v % HC;
#pragma unroll
                for (int i = 0; i < 4; i++) {
                    float2 p = unpack2(acc[j * 4 + i]);
                    sgp[(gate * 64 + (r0 + i)) * HC + jl] = p.x + p.y + gpre[i * 3 + j];
                }
            }
        }
        __syncthreads();

        // pointwise LSTM cell (sum both K-half planes; fast-math gates)
#pragma unroll
        for (int e = 0; e < 2; e++) {
            int idx = tid + e * PT;
            if (idx < 64 * HC) {
                int b = pb[e], jl = pjl[e];
                int o0 = (0 * 64 + b) * HC + jl;
                int o1 = (1 * 64 + b) * HC + jl;
                int o2 = (2 * 64 + b) * HC + jl;
                int o3 = (3 * 64 + b) * HC + jl;
                const int PL = 4 * 64 * HC;
                float ig = sg[o0] + sg[PL + o0];
                float fg = sg[o1] + sg[PL + o1];
                float gg = sg[o2] + sg[PL + o2];
                float og = sg[o3] + sg[PL + o3];
                float si = 1.f / (1.f + __expf(-ig));
                float sf = 1.f / (1.f + __expf(-fg));
                float so = 1.f / (1.f + __expf(-og));
                float e2g = __expf(2.f * gg);
                float tg = (e2g - 1.f) / (e2g + 1.f);
                float c2 = sf * cr[e] + si * tg;
                cr[e] = c2;
                float h = so * tanhf(c2);
                hwr[b * H_ + pj[e]] = h;
                dst[((size_t)b * S_ + t) * H_ + pj[e]] = h;
            }
        }

        // prefetch gpre for t+1 (group 0) before the barrier
        if (grp == 0 && t + 1 < S_) {
#pragma unroll
            for (int i = 0; i < 4; i++)
#pragma unroll
                for (int j = 0; j < 3; j++)
                    gpre[i * 3 + j] =
                        g_gates[((size_t)(r0 + i) * S_ + (t + 1)) * G_ + gcol[j]];
        }
        grid_barrier(gen);                   // publish h for next step
    }
}

// ---------------- split-K pool GEMM with atomic accumulation (pipelined) ----
#define BNA 64
#define BKA 16
__global__ void __launch_bounds__(256, 2) k_gemm_atomic(const float* __restrict__ W) {
    const float* A = g_act0;
    const int lda = S_ * H_, ldw = H_, klen = 4096, crow = H_;
    float* Cbase = g_pool;

    int nbase  = blockIdx.x * BNA;
    int kstart = blockIdx.y * klen;

    __shared__ float As[2][BKA][64 + 4];
    __shared__ float Ws[2][BKA][BNA];

    int tid = threadIdx.x;
    int tx = tid & 15, ty = tid >> 4;
    int m0 = ty * 4, n0 = tx * 4;

    int aR = tid >> 2, aC = (tid & 3) * 4;
    int wR = tid >> 4, wC = (tid & 15) * 4;

    ull acc[4][2];
#pragma unroll
    for (int i = 0; i < 4; i++) { acc[i][0] = 0ULL; acc[i][1] = 0ULL; }

    float4 rA, rW;
    rA = *(const float4*)(A + (size_t)aR * lda + kstart + aC);
    rW = *(const float4*)(W + (size_t)(kstart + wR) * ldw + nbase + wC);
    As[0][aC + 0][aR] = rA.x; As[0][aC + 1][aR] = rA.y;
    As[0][aC + 2][aR] = rA.z; As[0][aC + 3][aR] = rA.w;
    *(float4*)&Ws[0][wR][wC] = rW;

    int stage = 0;
    for (int k0 = kstart; k0 < kstart + klen; k0 += BKA) {
        __syncthreads();
        bool more = (k0 + BKA) < (kstart + klen);
        if (more) {
            rA = *(const float4*)(A + (size_t)aR * lda + (k0 + BKA) + aC);
            rW = *(const float4*)(W + (size_t)(k0 + BKA + wR) * ldw + nbase + wC);
        }
#pragma unroll
        for (int k = 0; k < BKA; k++) {
            float4 a4 = *(const float4*)&As[stage][k][m0];
            float4 b4 = *(const float4*)&Ws[stage][k][n0];
            ull b2l = pack2(b4.x, b4.y), b2h = pack2(b4.z, b4.w);
            float av[4] = { a4.x, a4.y, a4.z, a4.w };
#pragma unroll
            for (int i = 0; i < 4; i++) {
                ull ad = pack2(av[i], av[i]);
                acc[i][0] = fma2(ad, b2l, acc[i][0]);
                acc[i][1] = fma2(ad, b2h, acc[i][1]);
            }
        }
        if (more) {
            int ns = stage ^ 1;
            As[ns][aC + 0][aR] = rA.x; As[ns][aC + 1][aR] = rA.y;
            As[ns][aC + 2][aR] = rA.z; As[ns][aC + 3][aR] = rA.w;
            *(float4*)&Ws[ns][wR][wC] = rW;
            stage = ns;
        }
    }

#pragma unroll
    for (int i = 0; i < 4; i++) {
        float* Cp = Cbase + (size_t)(m0 + i) * crow + nbase + n0;
        float2 p0 = unpack2(acc[i][0]), p1 = unpack2(acc[i][1]);
        atomicAdd(Cp + 0, p0.x); atomicAdd(Cp + 1, p0.y);
        atomicAdd(Cp + 2, p1.x); atomicAdd(Cp + 3, p1.y);
    }
}

// ---------------- pool init: pool[b,n] = pool_b[n] --------------------------
__global__ void k_pool_init(const float* __restrict__ pb) {
    int u = blockIdx.x * blockDim.x + threadIdx.x;
    if (u < B_ * H_) g_pool[u] = pb[u % H_];
}

// ---------------- entity max + pooled max + logits (coalesced) --------------
__global__ void __launch_bounds__(256) k_final(const int* __restrict__ ent,
                                               const float* __restrict__ linW,
                                               const float* __restrict__ linb,
                                               float* __restrict__ out) {
    int b = blockIdx.x, tid = threadIdx.x;
    __shared__ float msk[S_];
    __shared__ float red0[256], red1[256];
    msk[tid] = (ent[b * S_ + tid] == 1) ? 1.f : 0.f;   // blockDim == S_
    __syncthreads();

    const float* base = g_act0 + (size_t)b * S_ * H_;
    float m0 = -INFINITY, m1 = -INFINITY, m2 = -INFINITY;
#pragma unroll 4
    for (int s = 0; s < S_; s++) {
        float mk = msk[s];
        const float* row = base + (size_t)s * H_;
        m0 = fmaxf(m0, row[tid]       * mk);
        m1 = fmaxf(m1, row[256 + tid] * mk);
        m2 = fmaxf(m2, row[512 + tid] * mk);
    }

    float p0 = 0.f, p1 = 0.f;
    float pooled;
    pooled = fmaxf(m0, g_pool[b * H_ + tid]);
    p0 += pooled * linW[tid * TOUT];         p1 += pooled * linW[tid * TOUT + 1];
    pooled = fmaxf(m1, g_pool[b * H_ + 256 + tid]);
    p0 += pooled * linW[(256 + tid) * TOUT]; p1 += pooled * linW[(256 + tid) * TOUT + 1];
    pooled = fmaxf(m2, g_pool[b * H_ + 512 + tid]);
    p0 += pooled * linW[(512 + tid) * TOUT]; p1 += pooled * linW[(512 + tid) * TOUT + 1];

    red0[tid] = p0; red1[tid] = p1;
    __syncthreads();
    for (int s = 128; s > 0; s >>= 1) {
        if (tid < s) { red0[tid] += red0[tid + s]; red1[tid] += red1[tid + s]; }
        __syncthreads();
    }
    if (tid == 0) {
        out[b * TOUT + 0] = red0[0] + linb[0];
        out[b * TOUT + 1] = red1[0] + linb[1];
    }
}

// ---------------- driver -----------------------------------------------------
extern "C" void kernel_launch(void* const* d_in, const int* in_sizes, int n_in,
                              void* d_out, int out_size) {
    const int*   ids   = (const int*)d_in[0];
    const int*   ent   = (const int*)d_in[4];
    const float* table = (const float*)d_in[5];
    const float* Wx0   = (const float*)d_in[6];
    const float* Wh0   = (const float*)d_in[7];
    const float* b0    = (const float*)d_in[8];
    const float* Wx1   = (const float*)d_in[9];
    const float* Wh1   = (const float*)d_in[10];
    const float* b1    = (const float*)d_in[11];
    const float* poolW = (const float*)d_in[12];
    const float* poolb = (const float*)d_in[13];
    const float* linW  = (const float*)d_in[14];
    const float* linb  = (const float*)d_in[15];
    float* out = (float*)d_out;

    const int persist_smem =
        (COLS * LDW + 2 * 64 * LDA + 2 * 4 * 64 * HC) * sizeof(float);  // ~119 KB
    cudaFuncSetAttribute(k_lstm_persist,
                         cudaFuncAttributeMaxDynamicSharedMemorySize, persist_smem);

    // 1. embedding
    k_embed<<<BS_, 192>>>(ids, table);

    // 2. layer 0: precompute x@Wx0 + b0 for all timesteps
    k_gemm_bias<<<dim3(G_ / BNB, BS_ / BM), 256>>>(0, Wx0, b0);

    // 3. layer 0 recurrence (persistent) -> g_act1
    k_lstm_persist<<<NBLK, PT, persist_smem>>>(Wh0, 1);

    // 4. layer 1: precompute x@Wx1 + b1
    k_gemm_bias<<<dim3(G_ / BNB, BS_ / BM), 256>>>(1, Wx1, b1);

    // 5. layer 1 recurrence -> g_act0
    k_lstm_persist<<<NBLK, PT, persist_smem>>>(Wh1, 0);

    // 6. pool = out.reshape(B, S*H) @ pool_W + pool_b   (split-K, atomic)
    k_pool_init<<<(B_ * H_ + 255) / 256, 256>>>(poolb);
    k_gemm_atomic<<<dim3(H_ / BNA, 48), 256>>>(poolW);

    // 7. entity max, pooled max, logits
    k_final<<<B_, 256>>>(ent, linW, linb, out);
}

// round 13
// speedup vs baseline: 1.5985x; 1.5985x over previous
#include <cuda_runtime.h>
#include <math.h>

// Problem constants
#define B_   64
#define S_   256
#define H_   768
#define G_   3072      // 4*H
#define BS_  16384     // B*S
#define TOUT 2

// Persistent recurrence config: each CTA owns all 64 rows, 6 h-cols / 24 gate-cols.
// 256 threads = 2 K-groups x 128; group g reduces K in [g*384, g*384+384).
// (R13 = R12 re-bench: R12's run was uniformly ~1.65x slower incl. the
//  byte-identical k_gemm_bias -> downclocked-GPU measurement, not a kernel delta.)
#define NBLK 128
#define PT   256
#define HC   6
#define COLS 24
#define CK   64        // K chunk per staging step (6 chunks per group)
#define KHALF 384
#define LDA  68        // As row stride (floats), 16B-aligned
#define LDW  772       // Ws row stride (floats), 16B-aligned, conflict-free B LDS.128

// ---------------- scratch (device globals; no allocation allowed) -----------
__device__ float g_act0[BS_ * H_];       // emb, later layer-1 output
__device__ float g_act1[BS_ * H_];       // layer-0 output
__device__ float g_gates[BS_ * G_];      // precomputed x@Wx + b
__device__ float g_hbuf[2][B_ * H_];     // double-buffered hidden state
__device__ float g_pool[B_ * H_];

__device__ unsigned g_bar_cnt = 0;
__device__ volatile unsigned g_bar_gen = 0;

// ---------------- packed f32x2 FMA helpers (Blackwell FFMA2) ----------------
typedef unsigned long long ull;

__device__ __forceinline__ ull fma2(ull a, ull b, ull c) {
    ull d;
    asm("fma.rn.f32x2 %0, %1, %2, %3;" : "=l"(d) : "l"(a), "l"(b), "l"(c));
    return d;
}
__device__ __forceinline__ float2 unpack2(ull v) {
    float x, y;
    asm("mov.b64 {%0, %1}, %2;" : "=f"(x), "=f"(y) : "l"(v));
    return make_float2(x, y);
}
__device__ __forceinline__ ull pack2(float x, float y) {
    ull r;
    asm("mov.b64 %0, {%1, %2};" : "=l"(r) : "f"(x), "f"(y));
    return r;
}

// group-scoped named barrier (128 threads each; ids 1 and 2)
#define GRP_BAR(g) asm volatile("bar.sync %0, 128;" :: "r"(1 + (g)) : "memory")

// ---------------- central grid barrier (all NBLK CTAs co-resident) ----------
__device__ __forceinline__ void grid_barrier(unsigned& gen) {
    __syncthreads();
    if (threadIdx.x == 0) {
        __threadfence();
        unsigned target = gen + 1u;
        unsigned old = atomicAdd(&g_bar_cnt, 1u);
        if (old == NBLK - 1) {
            g_bar_cnt = 0;
            __threadfence();
            g_bar_gen = target;
        } else {
            while (g_bar_gen != target) { __nanosleep(32); }
        }
        __threadfence();
    }
    __syncthreads();
    gen += 1u;
}

// ---------------- embedding gather ------------------------------------------
__global__ void k_embed(const int* __restrict__ ids, const float* __restrict__ table) {
    int row = blockIdx.x;
    int id  = ids[row];
    const float4* src = (const float4*)(table + (size_t)id * H_);
    float4*       dst = (float4*)(g_act0 + (size_t)row * H_);
    dst[threadIdx.x] = src[threadIdx.x];       // 192 threads * float4 = 768
}

// ---------------- big GEMM: gates = act @ Wx + bias (2-stage pipelined) -----
#define BM  128
#define BNB 128
#define BKB 16
__global__ void __launch_bounds__(256, 2) k_gemm_bias(int srcSel,
                                                      const float* __restrict__ Wx,
                                                      const float* __restrict__ bias) {
    const float* A = srcSel ? g_act1 : g_act0;
    __shared__ float As[2][BKB][BM + 4];
    __shared__ float Bs[2][BKB][BNB];

    int tid = threadIdx.x;
    int bm = blockIdx.y, bn = blockIdx.x;
    int tx = tid & 15, ty = tid >> 4;
    int m0 = ty * 8, n0 = tx * 8;

    int aR[2], aC[2], bR[2], bC[2];
#pragma unroll
    for (int it = 0; it < 2; it++) {
        int id = tid + it * 256;
        aR[it] = id >> 2;  aC[it] = (id & 3) * 4;
        bR[it] = id >> 5;  bC[it] = (id & 31) * 4;
    }

    ull acc[8][4];
#pragma unroll
    for (int i = 0; i < 8; i++)
#pragma unroll
        for (int j = 0; j < 4; j++) acc[i][j] = 0ULL;

    const float* Ab = A + (size_t)bm * BM * H_;
    const float* Wb = Wx + bn * BNB;

    float4 rA[2], rB[2];
#pragma unroll
    for (int it = 0; it < 2; it++) {
        rA[it] = *(const float4*)(Ab + (size_t)aR[it] * H_ + aC[it]);
        rB[it] = *(const float4*)(Wb + (size_t)bR[it] * G_ + bC[it]);
    }
#pragma unroll
    for (int it = 0; it < 2; it++) {
        As[0][aC[it] + 0][aR[it]] = rA[it].x;
        As[0][aC[it] + 1][aR[it]] = rA[it].y;
        As[0][aC[it] + 2][aR[it]] = rA[it].z;
        As[0][aC[it] + 3][aR[it]] = rA[it].w;
        *(float4*)&Bs[0][bR[it]][bC[it]] = rB[it];
    }

    int stage = 0;
    for (int k0 = 0; k0 < H_; k0 += BKB) {
        __syncthreads();
        bool more = (k0 + BKB) < H_;
        if (more) {
#pragma unroll
            for (int it = 0; it < 2; it++) {
                rA[it] = *(const float4*)(Ab + (size_t)aR[it] * H_ + (k0 + BKB) + aC[it]);
                rB[it] = *(const float4*)(Wb + (size_t)(k0 + BKB + bR[it]) * G_ + bC[it]);
            }
        }
#pragma unroll
        for (int k = 0; k < BKB; k++) {
            float4 alo = *(const float4*)&As[stage][k][m0];
            float4 ahi = *(const float4*)&As[stage][k][m0 + 4];
            float4 blo = *(const float4*)&Bs[stage][k][n0];
            float4 bhi = *(const float4*)&Bs[stage][k][n0 + 4];
            ull b2[4] = { pack2(blo.x, blo.y), pack2(blo.z, blo.w),
                          pack2(bhi.x, bhi.y), pack2(bhi.z, bhi.w) };
            float av[8] = { alo.x, alo.y, alo.z, alo.w, ahi.x, ahi.y, ahi.z, ahi.w };
#pragma unroll
            for (int i = 0; i < 8; i++) {
                ull ad = pack2(av[i], av[i]);
#pragma unroll
                for (int j = 0; j < 4; j++) acc[i][j] = fma2(ad, b2[j], acc[i][j]);
            }
        }
        if (more) {
            int ns = stage ^ 1;
#pragma unroll
            for (int it = 0; it < 2; it++) {
                As[ns][aC[it] + 0][aR[it]] = rA[it].x;
                As[ns][aC[it] + 1][aR[it]] = rA[it].y;
                As[ns][aC[it] + 2][aR[it]] = rA[it].z;
                As[ns][aC[it] + 3][aR[it]] = rA[it].w;
                *(float4*)&Bs[ns][bR[it]][bC[it]] = rB[it];
            }
            stage = ns;
        }
    }

    float bv[8];
#pragma unroll
    for (int j = 0; j < 8; j++) bv[j] = bias[bn * BNB + n0 + j];
#pragma unroll
    for (int i = 0; i < 8; i++) {
        float* Crow = g_gates + (size_t)(bm * BM + m0 + i) * G_ + bn * BNB + n0;
        float o[8];
#pragma unroll
        for (int j = 0; j < 4; j++) {
            float2 p = unpack2(acc[i][j]);
            o[2 * j]     = p.x + bv[2 * j];
            o[2 * j + 1] = p.y + bv[2 * j + 1];
        }
        *(float4*)(Crow)     = make_float4(o[0], o[1], o[2], o[3]);
        *(float4*)(Crow + 4) = make_float4(o[4], o[5], o[6], o[7]);
    }
}

// ---------------- persistent LSTM layer kernel (256 thr, K-split, LDS.128) --
__global__ void __launch_bounds__(PT, 1) k_lstm_persist(const float* __restrict__ Wh,
                                                        int dstSel) {
    extern __shared__ float sm[];
    float* Ws = sm;                          // [COLS][LDW]
    float* As = Ws + COLS * LDW;             // [2][64][LDA]  one buffer per group
    float* sg = As + 2 * 64 * LDA;           // [2][4*64*HC]  partial planes

    const int tid = threadIdx.x, bid = blockIdx.x;
    const int grp = tid >> 7, wt = tid & 127;
    float* dst = dstSel ? g_act1 : g_act0;

    // ---- load persistent Wh slice (gathered gate columns) ----
    for (int i = tid; i < COLS * H_; i += PT) {
        int v = i % COLS, k = i / COLS;
        int col = (v / HC) * H_ + bid * HC + (v % HC);
        Ws[v * LDW + k] = Wh[(size_t)k * G_ + col];
    }

    // ---- pointwise ownership: 384 elems over 256 threads (<=2 each) ----
    int pb[2], pj[2], pjl[2];
    float cr[2];
#pragma unroll
    for (int e = 0; e < 2; e++) {
        int idx = tid + e * PT;
        if (idx < 64 * HC) {
            pb[e]  = idx / HC;
            pjl[e] = idx % HC;
            pj[e]  = bid * HC + pjl[e];
            cr[e]  = 0.f;
            g_hbuf[0][pb[e] * H_ + pj[e]] = 0.f;   // t=0 reads buffer 0
        }
    }

    unsigned gen = g_bar_gen;
    grid_barrier(gen);                       // h zeroed + Ws loaded everywhere

    const int ty = wt >> 3, tx = wt & 7;
    const int r0 = ty * 4, n0 = tx * 3;      // 4 rows x 3 gate-cols per thread
    const int kbase = grp * KHALF;
    float* asg = As + grp * 64 * LDA;

    int gcol[3];
#pragma unroll
    for (int j = 0; j < 3; j++) {
        int v = n0 + j;
        gcol[j] = (v / HC) * H_ + bid * HC + (v % HC);
    }

    float gpre[12];
#pragma unroll
    for (int i = 0; i < 12; i++) gpre[i] = 0.f;
    if (grp == 0) {
#pragma unroll
        for (int i = 0; i < 4; i++)
#pragma unroll
            for (int j = 0; j < 3; j++)
                gpre[i * 3 + j] = g_gates[((size_t)(r0 + i) * S_) * G_ + gcol[j]];
    }

    for (int t = 0; t < S_; t++) {
        const float* hrd = g_hbuf[t & 1];
        float*       hwr = g_hbuf[(t + 1) & 1];

        // prefetch my group's chunk 0 (L1-bypassing)
        float4 pf[8];
#pragma unroll
        for (int ii = 0; ii < 8; ii++) {
            int i = wt + ii * 128;               // 0..1023 = 64 rows x 16 float4
            int r = i >> 4, c4 = (i & 15) << 2;
            pf[ii] = __ldcg((const float4*)(hrd + r * H_ + kbase + c4));
        }

        ull acc[12];
#pragma unroll
        for (int i = 0; i < 12; i++) acc[i] = 0ULL;

        for (int c = 0; c < KHALF / CK; c++) {
            GRP_BAR(grp);                    // group's prior compute done (WAR)
#pragma unroll
            for (int ii = 0; ii < 8; ii++) {
                int i = wt + ii * 128;
                int r = i >> 4, c4 = (i & 15) << 2;
                *(float4*)&asg[r * LDA + c4] = pf[ii];
            }
            GRP_BAR(grp);                    // group's chunk c visible
            if (c + 1 < KHALF / CK) {
#pragma unroll
                for (int ii = 0; ii < 8; ii++) {
                    int i = wt + ii * 128;
                    int r = i >> 4, c4 = (i & 15) << 2;
                    pf[ii] = __ldcg((const float4*)(hrd + r * H_ + kbase + (c + 1) * CK + c4));
                }
            }
            const float* asp = asg + r0 * LDA;
            const float* wsp = Ws + n0 * LDW + kbase + c * CK;
#pragma unroll 4
            for (int k4 = 0; k4 < CK; k4 += 4) {
                longlong2 A0 = *(const longlong2*)(asp + k4);
                longlong2 A1 = *(const longlong2*)(asp + LDA + k4);
                longlong2 A2 = *(const longlong2*)(asp + 2 * LDA + k4);
                longlong2 A3 = *(const longlong2*)(asp + 3 * LDA + k4);
                longlong2 B0 = *(const longlong2*)(wsp + k4);
                longlong2 B1 = *(const longlong2*)(wsp + LDW + k4);
                longlong2 B2 = *(const longlong2*)(wsp + 2 * LDW + k4);
                acc[0]  = fma2(A0.x, B0.x, acc[0]);  acc[1]  = fma2(A1.x, B0.x, acc[1]);
                acc[2]  = fma2(A2.x, B0.x, acc[2]);  acc[3]  = fma2(A3.x, B0.x, acc[3]);
                acc[4]  = fma2(A0.x, B1.x, acc[4]);  acc[5]  = fma2(A1.x, B1.x, acc[5]);
                acc[6]  = fma2(A2.x, B1.x, acc[6]);  acc[7]  = fma2(A3.x, B1.x, acc[7]);
                acc[8]  = fma2(A0.x, B2.x, acc[8]);  acc[9]  = fma2(A1.x, B2.x, acc[9]);
                acc[10] = fma2(A2.x, B2.x, acc[10]); acc[11] = fma2(A3.x, B2.x, acc[11]);
                acc[0]  = fma2(A0.y, B0.y, acc[0]);  acc[1]  = fma2(A1.y, B0.y, acc[1]);
                acc[2]  = fma2(A2.y, B0.y, acc[2]);  acc[3]  = fma2(A3.y, B0.y, acc[3]);
                acc[4]  = fma2(A0.y, B1.y, acc[4]);  acc[5]  = fma2(A1.y, B1.y, acc[5]);
                acc[6]  = fma2(A2.y, B1.y, acc[6]);  acc[7]  = fma2(A3.y, B1.y, acc[7]);
                acc[8]  = fma2(A0.y, B2.y, acc[8]);  acc[9]  = fma2(A1.y, B2.y, acc[9]);
                acc[10] = fma2(A2.y, B2.y, acc[10]); acc[11] = fma2(A3.y, B2.y, acc[11]);
            }
        }

        // write this group's partial sums (+ gpre on group 0)
        {
            float* sgp = sg + grp * (4 * 64 * HC);
#pragma unroll
            for (int j = 0; j < 3; j++) {
                int v = n0 + j;
                int gate = v / HC, jl = v % HC;
#pragma unroll
                for (int i = 0; i < 4; i++) {
                    float2 p = unpack2(acc[j * 4 + i]);
                    sgp[(gate * 64 + (r0 + i)) * HC + jl] = p.x + p.y + gpre[i * 3 + j];
                }
            }
        }
        __syncthreads();

        // pointwise LSTM cell (sum both K-half planes; fast-math gates)
#pragma unroll
        for (int e = 0; e < 2; e++) {
            int idx = tid + e * PT;
            if (idx < 64 * HC) {
                int b = pb[e], jl = pjl[e];
                int o0 = (0 * 64 + b) * HC + jl;
                int o1 = (1 * 64 + b) * HC + jl;
                int o2 = (2 * 64 + b) * HC + jl;
                int o3 = (3 * 64 + b) * HC + jl;
                const int PL = 4 * 64 * HC;
                float ig = sg[o0] + sg[PL + o0];
                float fg = sg[o1] + sg[PL + o1];
                float gg = sg[o2] + sg[PL + o2];
                float og = sg[o3] + sg[PL + o3];
                float si = 1.f / (1.f + __expf(-ig));
                float sf = 1.f / (1.f + __expf(-fg));
                float so = 1.f / (1.f + __expf(-og));
                float e2g = __expf(2.f * gg);
                float tg = (e2g - 1.f) / (e2g + 1.f);
                float c2 = sf * cr[e] + si * tg;
                cr[e] = c2;
                float h = so * tanhf(c2);
                hwr[b * H_ + pj[e]] = h;
                dst[((size_t)b * S_ + t) * H_ + pj[e]] = h;
            }
        }

        // prefetch gpre for t+1 (group 0) before the barrier
        if (grp == 0 && t + 1 < S_) {
#pragma unroll
            for (int i = 0; i < 4; i++)
#pragma unroll
                for (int j = 0; j < 3; j++)
                    gpre[i * 3 + j] =
                        g_gates[((size_t)(r0 + i) * S_ + (t + 1)) * G_ + gcol[j]];
        }
        grid_barrier(gen);                   // publish h for next step
    }
}

// ---------------- split-K pool GEMM with atomic accumulation (pipelined) ----
#define BNA 64
#define BKA 16
__global__ void __launch_bounds__(256, 2) k_gemm_atomic(const float* __restrict__ W) {
    const float* A = g_act0;
    const int lda = S_ * H_, ldw = H_, klen = 4096, crow = H_;
    float* Cbase = g_pool;

    int nbase  = blockIdx.x * BNA;
    int kstart = blockIdx.y * klen;

    __shared__ float As[2][BKA][64 + 4];
    __shared__ float Ws[2][BKA][BNA];

    int tid = threadIdx.x;
    int tx = tid & 15, ty = tid >> 4;
    int m0 = ty * 4, n0 = tx * 4;

    int aR = tid >> 2, aC = (tid & 3) * 4;
    int wR = tid >> 4, wC = (tid & 15) * 4;

    ull acc[4][2];
#pragma unroll
    for (int i = 0; i < 4; i++) { acc[i][0] = 0ULL; acc[i][1] = 0ULL; }

    float4 rA, rW;
    rA = *(const float4*)(A + (size_t)aR * lda + kstart + aC);
    rW = *(const float4*)(W + (size_t)(kstart + wR) * ldw + nbase + wC);
    As[0][aC + 0][aR] = rA.x; As[0][aC + 1][aR] = rA.y;
    As[0][aC + 2][aR] = rA.z; As[0][aC + 3][aR] = rA.w;
    *(float4*)&Ws[0][wR][wC] = rW;

    int stage = 0;
    for (int k0 = kstart; k0 < kstart + klen; k0 += BKA) {
        __syncthreads();
        bool more = (k0 + BKA) < (kstart + klen);
        if (more) {
            rA = *(const float4*)(A + (size_t)aR * lda + (k0 + BKA) + aC);
            rW = *(const float4*)(W + (size_t)(k0 + BKA + wR) * ldw + nbase + wC);
        }
#pragma unroll
        for (int k = 0; k < BKA; k++) {
            float4 a4 = *(const float4*)&As[stage][k][m0];
            float4 b4 = *(const float4*)&Ws[stage][k][n0];
            ull b2l = pack2(b4.x, b4.y), b2h = pack2(b4.z, b4.w);
            float av[4] = { a4.x, a4.y, a4.z, a4.w };
#pragma unroll
            for (int i = 0; i < 4; i++) {
                ull ad = pack2(av[i], av[i]);
                acc[i][0] = fma2(ad, b2l, acc[i][0]);
                acc[i][1] = fma2(ad, b2h, acc[i][1]);
            }
        }
        if (more) {
            int ns = stage ^ 1;
            As[ns][aC + 0][aR] = rA.x; As[ns][aC + 1][aR] = rA.y;
            As[ns][aC + 2][aR] = rA.z; As[ns][aC + 3][aR] = rA.w;
            *(float4*)&Ws[ns][wR][wC] = rW;
            stage = ns;
        }
    }

#pragma unroll
    for (int i = 0; i < 4; i++) {
        float* Cp = Cbase + (size_t)(m0 + i) * crow + nbase + n0;
        float2 p0 = unpack2(acc[i][0]), p1 = unpack2(acc[i][1]);
        atomicAdd(Cp + 0, p0.x); atomicAdd(Cp + 1, p0.y);
        atomicAdd(Cp + 2, p1.x); atomicAdd(Cp + 3, p1.y);
    }
}

// ---------------- pool init: pool[b,n] = pool_b[n] --------------------------
__global__ void k_pool_init(const float* __restrict__ pb) {
    int u = blockIdx.x * blockDim.x + threadIdx.x;
    if (u < B_ * H_) g_pool[u] = pb[u % H_];
}

// ---------------- entity max + pooled max + logits (coalesced) --------------
__global__ void __launch_bounds__(256) k_final(const int* __restrict__ ent,
                                               const float* __restrict__ linW,
                                               const float* __restrict__ linb,
                                               float* __restrict__ out) {
    int b = blockIdx.x, tid = threadIdx.x;
    __shared__ float msk[S_];
    __shared__ float red0[256], red1[256];
    msk[tid] = (ent[b * S_ + tid] == 1) ? 1.f : 0.f;   // blockDim == S_
    __syncthreads();

    const float* base = g_act0 + (size_t)b * S_ * H_;
    float m0 = -INFINITY, m1 = -INFINITY, m2 = -INFINITY;
#pragma unroll 4
    for (int s = 0; s < S_; s++) {
        float mk = msk[s];
        const float* row = base + (size_t)s * H_;
        m0 = fmaxf(m0, row[tid]       * mk);
        m1 = fmaxf(m1, row[256 + tid] * mk);
        m2 = fmaxf(m2, row[512 + tid] * mk);
    }

    float p0 = 0.f, p1 = 0.f;
    float pooled;
    pooled = fmaxf(m0, g_pool[b * H_ + tid]);
    p0 += pooled * linW[tid * TOUT];         p1 += pooled * linW[tid * TOUT + 1];
    pooled = fmaxf(m1, g_pool[b * H_ + 256 + tid]);
    p0 += pooled * linW[(256 + tid) * TOUT]; p1 += pooled * linW[(256 + tid) * TOUT + 1];
    pooled = fmaxf(m2, g_pool[b * H_ + 512 + tid]);
    p0 += pooled * linW[(512 + tid) * TOUT]; p1 += pooled * linW[(512 + tid) * TOUT + 1];

    red0[tid] = p0; red1[tid] = p1;
    __syncthreads();
    for (int s = 128; s > 0; s >>= 1) {
        if (tid < s) { red0[tid] += red0[tid + s]; red1[tid] += red1[tid + s]; }
        __syncthreads();
    }
    if (tid == 0) {
        out[b * TOUT + 0] = red0[0] + linb[0];
        out[b * TOUT + 1] = red1[0] + linb[1];
    }
}

// ---------------- driver -----------------------------------------------------
extern "C" void kernel_launch(void* const* d_in, const int* in_sizes, int n_in,
                              void* d_out, int out_size) {
    const int*   ids   = (const int*)d_in[0];
    const int*   ent   = (const int*)d_in[4];
    const float* table = (const float*)d_in[5];
    const float* Wx0   = (const float*)d_in[6];
    const float* Wh0   = (const float*)d_in[7];
    const float* b0    = (const float*)d_in[8];
    const float* Wx1   = (const float*)d_in[9];
    const float* Wh1   = (const float*)d_in[10];
    const float* b1    = (const float*)d_in[11];
    const float* poolW = (const float*)d_in[12];
    const float* poolb = (const float*)d_in[13];
    const float* linW  = (const float*)d_in[14];
    const float* linb  = (const float*)d_in[15];
    float* out = (float*)d_out;

    const int persist_smem =
        (COLS * LDW + 2 * 64 * LDA + 2 * 4 * 64 * HC) * sizeof(float);  // ~119 KB
    cudaFuncSetAttribute(k_lstm_persist,
                         cudaFuncAttributeMaxDynamicSharedMemorySize, persist_smem);

    // 1. embedding
    k_embed<<<BS_, 192>>>(ids, table);

    // 2. layer 0: precompute x@Wx0 + b0 for all timesteps
    k_gemm_bias<<<dim3(G_ / BNB, BS_ / BM), 256>>>(0, Wx0, b0);

    // 3. layer 0 recurrence (persistent) -> g_act1
    k_lstm_persist<<<NBLK, PT, persist_smem>>>(Wh0, 1);

    // 4. layer 1: precompute x@Wx1 + b1
    k_gemm_bias<<<dim3(G_ / BNB, BS_ / BM), 256>>>(1, Wx1, b1);

    // 5. layer 1 recurrence -> g_act0
    k_lstm_persist<<<NBLK, PT, persist_smem>>>(Wh1, 0);

    // 6. pool = out.reshape(B, S*H) @ pool_W + pool_b   (split-K, atomic)
    k_pool_init<<<(B_ * H_ + 255) / 256, 256>>>(poolb);
    k_gemm_atomic<<<dim3(H_ / BNA, 48), 256>>>(poolW);

    // 7. entity max, pooled max, logits
    k_final<<<B_, 256>>>(ent, linW, linb, out);
}

// round 15
// speedup vs baseline: 1.7528x; 1.0965x over previous
#include <cuda_runtime.h>
#include <math.h>

// Problem constants
#define B_   64
#define S_   256
#define H_   768
#define G_   3072      // 4*H
#define BS_  16384     // B*S
#define TOUT 2

// Persistent recurrence config: each CTA owns all 64 rows, 6 h-cols / 24 gate-cols.
// 384 threads = 3 K-groups x 128; group g reduces K in [g*256, g*256+256).
// (R15 = R14 resubmission: R14 never ran — GB300 container failed twice.)
#define NBLK 128
#define PT   384
#define HC   6
#define COLS 24
#define CK   64        // K chunk per staging step (4 chunks per group)
#define KTHIRD 256
#define LDA  68        // As row stride (floats)
#define LDW  770       // Ws row stride (floats)

// ---------------- scratch (device globals; no allocation allowed) -----------
__device__ float g_act0[BS_ * H_];       // emb, later layer-1 output
__device__ float g_act1[BS_ * H_];       // layer-0 output
__device__ float g_gates[BS_ * G_];      // precomputed x@Wx + b
__device__ float g_hbuf[2][B_ * H_];     // double-buffered hidden state
__device__ float g_pool[B_ * H_];

__device__ unsigned g_bar_cnt = 0;
__device__ volatile unsigned g_bar_gen = 0;

// ---------------- packed f32x2 FMA helpers (Blackwell FFMA2) ----------------
typedef unsigned long long ull;

__device__ __forceinline__ ull fma2(ull a, ull b, ull c) {
    ull d;
    asm("fma.rn.f32x2 %0, %1, %2, %3;" : "=l"(d) : "l"(a), "l"(b), "l"(c));
    return d;
}
__device__ __forceinline__ float2 unpack2(ull v) {
    float x, y;
    asm("mov.b64 {%0, %1}, %2;" : "=f"(x), "=f"(y) : "l"(v));
    return make_float2(x, y);
}
__device__ __forceinline__ ull pack2(float x, float y) {
    ull r;
    asm("mov.b64 %0, {%1, %2};" : "=l"(r) : "f"(x), "f"(y));
    return r;
}

// group-scoped named barrier (128 threads each; ids 1..3)
#define GRP_BAR(g) asm volatile("bar.sync %0, 128;" :: "r"(1 + (g)) : "memory")

// ---------------- central grid barrier (all NBLK CTAs co-resident) ----------
__device__ __forceinline__ void grid_barrier(unsigned& gen) {
    __syncthreads();
    if (threadIdx.x == 0) {
        __threadfence();
        unsigned target = gen + 1u;
        unsigned old = atomicAdd(&g_bar_cnt, 1u);
        if (old == NBLK - 1) {
            g_bar_cnt = 0;
            __threadfence();
            g_bar_gen = target;
        } else {
            while (g_bar_gen != target) { __nanosleep(32); }
        }
        __threadfence();
    }
    __syncthreads();
    gen += 1u;
}

// ---------------- embedding gather ------------------------------------------
__global__ void k_embed(const int* __restrict__ ids, const float* __restrict__ table) {
    int row = blockIdx.x;
    int id  = ids[row];
    const float4* src = (const float4*)(table + (size_t)id * H_);
    float4*       dst = (float4*)(g_act0 + (size_t)row * H_);
    dst[threadIdx.x] = src[threadIdx.x];       // 192 threads * float4 = 768
}

// ---------------- big GEMM: gates = act @ Wx + bias (2-stage pipelined) -----
#define BM  128
#define BNB 128
#define BKB 16
__global__ void __launch_bounds__(256, 2) k_gemm_bias(int srcSel,
                                                      const float* __restrict__ Wx,
                                                      const float* __restrict__ bias) {
    const float* A = srcSel ? g_act1 : g_act0;
    __shared__ float As[2][BKB][BM + 4];
    __shared__ float Bs[2][BKB][BNB];

    int tid = threadIdx.x;
    int bm = blockIdx.y, bn = blockIdx.x;
    int tx = tid & 15, ty = tid >> 4;
    int m0 = ty * 8, n0 = tx * 8;

    int aR[2], aC[2], bR[2], bC[2];
#pragma unroll
    for (int it = 0; it < 2; it++) {
        int id = tid + it * 256;
        aR[it] = id >> 2;  aC[it] = (id & 3) * 4;
        bR[it] = id >> 5;  bC[it] = (id & 31) * 4;
    }

    ull acc[8][4];
#pragma unroll
    for (int i = 0; i < 8; i++)
#pragma unroll
        for (int j = 0; j < 4; j++) acc[i][j] = 0ULL;

    const float* Ab = A + (size_t)bm * BM * H_;
    const float* Wb = Wx + bn * BNB;

    float4 rA[2], rB[2];
#pragma unroll
    for (int it = 0; it < 2; it++) {
        rA[it] = *(const float4*)(Ab + (size_t)aR[it] * H_ + aC[it]);
        rB[it] = *(const float4*)(Wb + (size_t)bR[it] * G_ + bC[it]);
    }
#pragma unroll
    for (int it = 0; it < 2; it++) {
        As[0][aC[it] + 0][aR[it]] = rA[it].x;
        As[0][aC[it] + 1][aR[it]] = rA[it].y;
        As[0][aC[it] + 2][aR[it]] = rA[it].z;
        As[0][aC[it] + 3][aR[it]] = rA[it].w;
        *(float4*)&Bs[0][bR[it]][bC[it]] = rB[it];
    }

    int stage = 0;
    for (int k0 = 0; k0 < H_; k0 += BKB) {
        __syncthreads();
        bool more = (k0 + BKB) < H_;
        if (more) {
#pragma unroll
            for (int it = 0; it < 2; it++) {
                rA[it] = *(const float4*)(Ab + (size_t)aR[it] * H_ + (k0 + BKB) + aC[it]);
                rB[it] = *(const float4*)(Wb + (size_t)(k0 + BKB + bR[it]) * G_ + bC[it]);
            }
        }
#pragma unroll
        for (int k = 0; k < BKB; k++) {
            float4 alo = *(const float4*)&As[stage][k][m0];
            float4 ahi = *(const float4*)&As[stage][k][m0 + 4];
            float4 blo = *(const float4*)&Bs[stage][k][n0];
            float4 bhi = *(const float4*)&Bs[stage][k][n0 + 4];
            ull b2[4] = { pack2(blo.x, blo.y), pack2(blo.z, blo.w),
                          pack2(bhi.x, bhi.y), pack2(bhi.z, bhi.w) };
            float av[8] = { alo.x, alo.y, alo.z, alo.w, ahi.x, ahi.y, ahi.z, ahi.w };
#pragma unroll
            for (int i = 0; i < 8; i++) {
                ull ad = pack2(av[i], av[i]);
#pragma unroll
                for (int j = 0; j < 4; j++) acc[i][j] = fma2(ad, b2[j], acc[i][j]);
            }
        }
        if (more) {
            int ns = stage ^ 1;
#pragma unroll
            for (int it = 0; it < 2; it++) {
                As[ns][aC[it] + 0][aR[it]] = rA[it].x;
                As[ns][aC[it] + 1][aR[it]] = rA[it].y;
                As[ns][aC[it] + 2][aR[it]] = rA[it].z;
                As[ns][aC[it] + 3][aR[it]] = rA[it].w;
                *(float4*)&Bs[ns][bR[it]][bC[it]] = rB[it];
            }
            stage = ns;
        }
    }

    float bv[8];
#pragma unroll
    for (int j = 0; j < 8; j++) bv[j] = bias[bn * BNB + n0 + j];
#pragma unroll
    for (int i = 0; i < 8; i++) {
        float* Crow = g_gates + (size_t)(bm * BM + m0 + i) * G_ + bn * BNB + n0;
        float o[8];
#pragma unroll
        for (int j = 0; j < 4; j++) {
            float2 p = unpack2(acc[i][j]);
            o[2 * j]     = p.x + bv[2 * j];
            o[2 * j + 1] = p.y + bv[2 * j + 1];
        }
        *(float4*)(Crow)     = make_float4(o[0], o[1], o[2], o[3]);
        *(float4*)(Crow + 4) = make_float4(o[4], o[5], o[6], o[7]);
    }
}

// ---------------- persistent LSTM layer kernel (384 thr, 3 K-groups) --------
// R11 structure with a third K-group: group g owns K [g*256, g*256+256),
// stages in 4 chunks of 64 into its own As buffer (LDS.64 inner loop, the
// best measured form), writes a partial sg plane; pointwise sums 3 planes.
__global__ void __launch_bounds__(PT, 1) k_lstm_persist(const float* __restrict__ Wh,
                                                        int dstSel) {
    extern __shared__ float sm[];
    float* Ws = sm;                          // [COLS][LDW]
    float* As = Ws + COLS * LDW;             // [3][64][LDA]  one buffer per group
    float* sg = As + 3 * 64 * LDA;           // [3][4*64*HC]  partial planes

    const int tid = threadIdx.x, bid = blockIdx.x;
    const int grp = tid / 128, wt = tid % 128;
    float* dst = dstSel ? g_act1 : g_act0;

    // ---- load persistent Wh slice (gathered gate columns) ----
    for (int i = tid; i < COLS * H_; i += PT) {
        int v = i % COLS, k = i / COLS;
        int col = (v / HC) * H_ + bid * HC + (v % HC);
        Ws[v * LDW + k] = Wh[(size_t)k * G_ + col];
    }

    // ---- pointwise ownership: 384 elems, exactly 1 per thread ----
    const int pbb  = tid / HC;               // batch row 0..63
    const int pjl  = tid % HC;               // local h-col
    const int pjj  = bid * HC + pjl;         // global h-col
    float cr = 0.f;
    g_hbuf[0][pbb * H_ + pjj] = 0.f;         // t=0 reads buffer 0

    unsigned gen = g_bar_gen;
    grid_barrier(gen);                       // h zeroed + Ws loaded everywhere

    const int ty = wt >> 3, tx = wt & 7;
    const int r0 = ty * 4, n0 = tx * 3;      // 4 rows x 3 gate-cols per thread
    const int kbase = grp * KTHIRD;
    float* asg = As + grp * 64 * LDA;

    int gcol[3];
#pragma unroll
    for (int j = 0; j < 3; j++) {
        int v = n0 + j;
        gcol[j] = (v / HC) * H_ + bid * HC + (v % HC);
    }

    float gpre[12];
#pragma unroll
    for (int i = 0; i < 12; i++) gpre[i] = 0.f;
    if (grp == 0) {
#pragma unroll
        for (int i = 0; i < 4; i++)
#pragma unroll
            for (int j = 0; j < 3; j++)
                gpre[i * 3 + j] = g_gates[((size_t)(r0 + i) * S_) * G_ + gcol[j]];
    }

    for (int t = 0; t < S_; t++) {
        const float* hrd = g_hbuf[t & 1];
        float*       hwr = g_hbuf[(t + 1) & 1];

        // prefetch my group's chunk 0 (L1-bypassing)
        float4 pf[8];
#pragma unroll
        for (int ii = 0; ii < 8; ii++) {
            int i = wt + ii * 128;               // 0..1023 = 64 rows x 16 float4
            int r = i >> 4, c4 = (i & 15) << 2;
            pf[ii] = __ldcg((const float4*)(hrd + r * H_ + kbase + c4));
        }

        ull acc[12];
#pragma unroll
        for (int i = 0; i < 12; i++) acc[i] = 0ULL;

        for (int c = 0; c < KTHIRD / CK; c++) {
            GRP_BAR(grp);                    // group's prior compute done (WAR)
#pragma unroll
            for (int ii = 0; ii < 8; ii++) {
                int i = wt + ii * 128;
                int r = i >> 4, c4 = (i & 15) << 2;
                *(float4*)&asg[r * LDA + c4] = pf[ii];
            }
            GRP_BAR(grp);                    // group's chunk c visible
            if (c + 1 < KTHIRD / CK) {
#pragma unroll
                for (int ii = 0; ii < 8; ii++) {
                    int i = wt + ii * 128;
                    int r = i >> 4, c4 = (i & 15) << 2;
                    pf[ii] = __ldcg((const float4*)(hrd + r * H_ + kbase + (c + 1) * CK + c4));
                }
            }
            const float* asp = asg + r0 * LDA;
            const float* wsp = Ws + n0 * LDW + kbase + c * CK;
#pragma unroll 16
            for (int kk = 0; kk < CK / 2; kk++) {
                int k2 = kk * 2;
                ull a0 = *(const ull*)(asp + 0 * LDA + k2);
                ull a1 = *(const ull*)(asp + 1 * LDA + k2);
                ull a2 = *(const ull*)(asp + 2 * LDA + k2);
                ull a3 = *(const ull*)(asp + 3 * LDA + k2);
                ull b0 = *(const ull*)(wsp + 0 * LDW + k2);
                ull b1 = *(const ull*)(wsp + 1 * LDW + k2);
                ull b2 = *(const ull*)(wsp + 2 * LDW + k2);
                acc[0]  = fma2(a0, b0, acc[0]);  acc[1]  = fma2(a1, b0, acc[1]);
                acc[2]  = fma2(a2, b0, acc[2]);  acc[3]  = fma2(a3, b0, acc[3]);
                acc[4]  = fma2(a0, b1, acc[4]);  acc[5]  = fma2(a1, b1, acc[5]);
                acc[6]  = fma2(a2, b1, acc[6]);  acc[7]  = fma2(a3, b1, acc[7]);
                acc[8]  = fma2(a0, b2, acc[8]);  acc[9]  = fma2(a1, b2, acc[9]);
                acc[10] = fma2(a2, b2, acc[10]); acc[11] = fma2(a3, b2, acc[11]);
            }
        }

        // write this group's partial sums (+ gpre on group 0)
        {
            float* sgp = sg + grp * (4 * 64 * HC);
#pragma unroll
            for (int j = 0; j < 3; j++) {
                int v = n0 + j;
                int gate = v / HC, jl = v % HC;
#pragma unroll
                for (int i = 0; i < 4; i++) {
                    float2 p = unpack2(acc[j * 4 + i]);
                    sgp[(gate * 64 + (r0 + i)) * HC + jl] = p.x + p.y + gpre[i * 3 + j];
                }
            }
        }
        __syncthreads();

        // pointwise LSTM cell (sum all 3 K-planes; fast-math gates)
        {
            const int PL = 4 * 64 * HC;
            int o0 = (0 * 64 + pbb) * HC + pjl;
            int o1 = (1 * 64 + pbb) * HC + pjl;
            int o2 = (2 * 64 + pbb) * HC + pjl;
            int o3 = (3 * 64 + pbb) * HC + pjl;
            float ig = sg[o0] + sg[PL + o0] + sg[2 * PL + o0];
            float fg = sg[o1] + sg[PL + o1] + sg[2 * PL + o1];
            float gg = sg[o2] + sg[PL + o2] + sg[2 * PL + o2];
            float og = sg[o3] + sg[PL + o3] + sg[2 * PL + o3];
            float si = 1.f / (1.f + __expf(-ig));
            float sf = 1.f / (1.f + __expf(-fg));
            float so = 1.f / (1.f + __expf(-og));
            float e2g = __expf(2.f * gg);
            float tg = (e2g - 1.f) / (e2g + 1.f);
            float c2 = sf * cr + si * tg;
            cr = c2;
            float h = so * tanhf(c2);
            hwr[pbb * H_ + pjj] = h;
            dst[((size_t)pbb * S_ + t) * H_ + pjj] = h;
        }

        // prefetch gpre for t+1 (group 0) before the barrier
        if (grp == 0 && t + 1 < S_) {
#pragma unroll
            for (int i = 0; i < 4; i++)
#pragma unroll
                for (int j = 0; j < 3; j++)
                    gpre[i * 3 + j] =
                        g_gates[((size_t)(r0 + i) * S_ + (t + 1)) * G_ + gcol[j]];
        }
        grid_barrier(gen);                   // publish h for next step
    }
}

// ---------------- split-K pool GEMM with atomic accumulation (pipelined) ----
#define BNA 64
#define BKA 16
__global__ void __launch_bounds__(256, 2) k_gemm_atomic(const float* __restrict__ W) {
    const float* A = g_act0;
    const int lda = S_ * H_, ldw = H_, klen = 4096, crow = H_;
    float* Cbase = g_pool;

    int nbase  = blockIdx.x * BNA;
    int kstart = blockIdx.y * klen;

    __shared__ float As[2][BKA][64 + 4];
    __shared__ float Ws[2][BKA][BNA];

    int tid = threadIdx.x;
    int tx = tid & 15, ty = tid >> 4;
    int m0 = ty * 4, n0 = tx * 4;

    int aR = tid >> 2, aC = (tid & 3) * 4;
    int wR = tid >> 4, wC = (tid & 15) * 4;

    ull acc[4][2];
#pragma unroll
    for (int i = 0; i < 4; i++) { acc[i][0] = 0ULL; acc[i][1] = 0ULL; }

    float4 rA, rW;
    rA = *(const float4*)(A + (size_t)aR * lda + kstart + aC);
    rW = *(const float4*)(W + (size_t)(kstart + wR) * ldw + nbase + wC);
    As[0][aC + 0][aR] = rA.x; As[0][aC + 1][aR] = rA.y;
    As[0][aC + 2][aR] = rA.z; As[0][aC + 3][aR] = rA.w;
    *(float4*)&Ws[0][wR][wC] = rW;

    int stage = 0;
    for (int k0 = kstart; k0 < kstart + klen; k0 += BKA) {
        __syncthreads();
        bool more = (k0 + BKA) < (kstart + klen);
        if (more) {
            rA = *(const float4*)(A + (size_t)aR * lda + (k0 + BKA) + aC);
            rW = *(const float4*)(W + (size_t)(k0 + BKA + wR) * ldw + nbase + wC);
        }
#pragma unroll
        for (int k = 0; k < BKA; k++) {
            float4 a4 = *(const float4*)&As[stage][k][m0];
            float4 b4 = *(const float4*)&Ws[stage][k][n0];
            ull b2l = pack2(b4.x, b4.y), b2h = pack2(b4.z, b4.w);
            float av[4] = { a4.x, a4.y, a4.z, a4.w };
#pragma unroll
            for (int i = 0; i < 4; i++) {
                ull ad = pack2(av[i], av[i]);
                acc[i][0] = fma2(ad, b2l, acc[i][0]);
                acc[i][1] = fma2(ad, b2h, acc[i][1]);
            }
        }
        if (more) {
            int ns = stage ^ 1;
            As[ns][aC + 0][aR] = rA.x; As[ns][aC + 1][aR] = rA.y;
            As[ns][aC + 2][aR] = rA.z; As[ns][aC + 3][aR] = rA.w;
            *(float4*)&Ws[ns][wR][wC] = rW;
            stage = ns;
        }
    }

#pragma unroll
    for (int i = 0; i < 4; i++) {
        float* Cp = Cbase + (size_t)(m0 + i) * crow + nbase + n0;
        float2 p0 = unpack2(acc[i][0]), p1 = unpack2(acc[i][1]);
        atomicAdd(Cp + 0, p0.x); atomicAdd(Cp + 1, p0.y);
        atomicAdd(Cp + 2, p1.x); atomicAdd(Cp + 3, p1.y);
    }
}

// ---------------- pool init: pool[b,n] = pool_b[n] --------------------------
__global__ void k_pool_init(const float* __restrict__ pb) {
    int u = blockIdx.x * blockDim.x + threadIdx.x;
    if (u < B_ * H_) g_pool[u] = pb[u % H_];
}

// ---------------- entity max + pooled max + logits (coalesced) --------------
__global__ void __launch_bounds__(256) k_final(const int* __restrict__ ent,
                                               const float* __restrict__ linW,
                                               const float* __restrict__ linb,
                                               float* __restrict__ out) {
    int b = blockIdx.x, tid = threadIdx.x;
    __shared__ float msk[S_];
    __shared__ float red0[256], red1[256];
    msk[tid] = (ent[b * S_ + tid] == 1) ? 1.f : 0.f;   // blockDim == S_
    __syncthreads();

    const float* base = g_act0 + (size_t)b * S_ * H_;
    float m0 = -INFINITY, m1 = -INFINITY, m2 = -INFINITY;
#pragma unroll 4
    for (int s = 0; s < S_; s++) {
        float mk = msk[s];
        const float* row = base + (size_t)s * H_;
        m0 = fmaxf(m0, row[tid]       * mk);
        m1 = fmaxf(m1, row[256 + tid] * mk);
        m2 = fmaxf(m2, row[512 + tid] * mk);
    }

    float p0 = 0.f, p1 = 0.f;
    float pooled;
    pooled = fmaxf(m0, g_pool[b * H_ + tid]);
    p0 += pooled * linW[tid * TOUT];         p1 += pooled * linW[tid * TOUT + 1];
    pooled = fmaxf(m1, g_pool[b * H_ + 256 + tid]);
    p0 += pooled * linW[(256 + tid) * TOUT]; p1 += pooled * linW[(256 + tid) * TOUT + 1];
    pooled = fmaxf(m2, g_pool[b * H_ + 512 + tid]);
    p0 += pooled * linW[(512 + tid) * TOUT]; p1 += pooled * linW[(512 + tid) * TOUT + 1];

    red0[tid] = p0; red1[tid] = p1;
    __syncthreads();
    for (int s = 128; s > 0; s >>= 1) {
        if (tid < s) { red0[tid] += red0[tid + s]; red1[tid] += red1[tid + s]; }
        __syncthreads();
    }
    if (tid == 0) {
        out[b * TOUT + 0] = red0[0] + linb[0];
        out[b * TOUT + 1] = red1[0] + linb[1];
    }
}

// ---------------- driver -----------------------------------------------------
extern "C" void kernel_launch(void* const* d_in, const int* in_sizes, int n_in,
                              void* d_out, int out_size) {
    const int*   ids   = (const int*)d_in[0];
    const int*   ent   = (const int*)d_in[4];
    const float* table = (const float*)d_in[5];
    const float* Wx0   = (const float*)d_in[6];
    const float* Wh0   = (const float*)d_in[7];
    const float* b0    = (const float*)d_in[8];
    const float* Wx1   = (const float*)d_in[9];
    const float* Wh1   = (const float*)d_in[10];
    const float* b1    = (const float*)d_in[11];
    const float* poolW = (const float*)d_in[12];
    const float* poolb = (const float*)d_in[13];
    const float* linW  = (const float*)d_in[14];
    const float* linb  = (const float*)d_in[15];
    float* out = (float*)d_out;

    const int persist_smem =
        (COLS * LDW + 3 * 64 * LDA + 3 * 4 * 64 * HC) * sizeof(float);  // ~145 KB
    cudaFuncSetAttribute(k_lstm_persist,
                         cudaFuncAttributeMaxDynamicSharedMemorySize, persist_smem);

    // 1. embedding
    k_embed<<<BS_, 192>>>(ids, table);

    // 2. layer 0: precompute x@Wx0 + b0 for all timesteps
    k_gemm_bias<<<dim3(G_ / BNB, BS_ / BM), 256>>>(0, Wx0, b0);

    // 3. layer 0 recurrence (persistent) -> g_act1
    k_lstm_persist<<<NBLK, PT, persist_smem>>>(Wh0, 1);

    // 4. layer 1: precompute x@Wx1 + b1
    k_gemm_bias<<<dim3(G_ / BNB, BS_ / BM), 256>>>(1, Wx1, b1);

    // 5. layer 1 recurrence -> g_act0
    k_lstm_persist<<<NBLK, PT, persist_smem>>>(Wh1, 0);

    // 6. pool = out.reshape(B, S*H) @ pool_W + pool_b   (split-K, atomic)
    k_pool_init<<<(B_ * H_ + 255) / 256, 256>>>(poolb);
    k_gemm_atomic<<<dim3(H_ / BNA, 48), 256>>>(poolW);

    // 7. entity max, pooled max, logits
    k_final<<<B_, 256>>>(ent, linW, linb, out);
}